// round 11
// baseline (speedup 1.0000x reference)
#include <cuda_runtime.h>
#include <math.h>
#include <stdint.h>

#define B 16
#define S 4096
#define H 1024
#define JC 64                  // rows per block chunk
#define NCHUNK (S / JC)        // 64 chunks per batch
#define TILE 8                 // rows per smem tile
#define NTILE (JC / TILE)      // 8 tiles per chunk
#define NTHREAD 256

// ---- device scratch (no allocations allowed) ----
__device__ float    g_pm[B * NCHUNK];               // per-chunk max
__device__ float    g_pl[B * NCHUNK];               // per-chunk denom partial
__device__ float    g_pacc[(size_t)B * NCHUNK * H]; // per-chunk numerator (4 MB)
__device__ unsigned g_cnt[B];                       // accumulating arrival counters

// cp.async helpers
__device__ __forceinline__ void cp16(uint32_t saddr, const void* g) {
    asm volatile("cp.async.cg.shared.global [%0], [%1], 16;\n" :: "r"(saddr), "l"(g));
}
__device__ __forceinline__ void cp_commit() { asm volatile("cp.async.commit_group;\n"); }
__device__ __forceinline__ void cp_wait1()  { asm volatile("cp.async.wait_group 1;\n" ::: "memory"); }
__device__ __forceinline__ void cp_wait0()  { asm volatile("cp.async.wait_group 0;\n" ::: "memory"); }

// query_indices decode: auto-detect int32 vs int64 storage.
__device__ __forceinline__ bool qi_is64(const int* __restrict__ qi) {
#pragma unroll
    for (int i = 1; i < 32; i += 2)
        if (qi[i] != 0) return false;
    return true;
}
__device__ __forceinline__ void qi_decode(const int* __restrict__ qi, bool is64,
                                          int b, int& s, int& e) {
    if (is64) { s = qi[4 * b]; e = qi[4 * b + 2]; }
    else      { s = qi[2 * b]; e = qi[2 * b + 1]; }
}

// stage one 8-row tile into smem: thread tid loads column-float4 `tid` of each row
__device__ __forceinline__ void issue_tile(const float* __restrict__ rowbase,
                                           int jt, int jend, uint32_t sbuf, int tid) {
#pragma unroll
    for (int i = 0; i < TILE; i++) {
        if (jt + i < jend)
            cp16(sbuf + (uint32_t)(i * 256 + tid) * 16,
                 rowbase + (size_t)(jt + i) * H + tid * 4);
    }
}

__global__ void __launch_bounds__(NTHREAD) k_main(const float* __restrict__ hs,
                                                  const int*   __restrict__ qi,
                                                  const float* __restrict__ am,
                                                  const float* __restrict__ w,
                                                  float*       __restrict__ out) {
    extern __shared__ float dsm[];
    float* buf[2];
    buf[0] = dsm;                       // 8192 floats (8 rows x 1024)
    buf[1] = dsm + TILE * H;            // 8192 floats
    float* swv   = dsm + 2 * TILE * H;  // 1024 (w)
    float* sdot  = swv + H;             // 8  raw scores
    float* pbuf  = sdot + 8;            // 8  softmax weights
    float* sscal = pbuf + 8;            // [0]=fac, [1]=m_s
    float* sred  = sscal + 2;           // 256 (combine)
    float* sfac  = sred + NTHREAD;      // 64  (combine)
    unsigned* s_last = (unsigned*)(sfac + NCHUNK);

    const int b     = blockIdx.y;
    const int chunk = blockIdx.x;
    const int pidx  = b * NCHUNK + chunk;
    const int tid   = threadIdx.x;
    const int warp  = tid >> 5;
    const int lane  = tid & 31;

    const bool is64 = qi_is64(qi);
    int s0, e0; qi_decode(qi, is64, b, s0, e0);
    const int qlen  = e0 - s0;
    const int jbase = chunk * JC;
    const bool active = jbase < qlen;

    float l_acc = 0.0f;     // valid on (warp0, lane0) only
    float m_reg = -INFINITY;

    if (active) {
        const int jend   = min(jbase + JC, qlen);
        const int ntiles = (jend - jbase + TILE - 1) / TILE;
        const float amb  = am[b];
        const float* rowbase = hs + ((size_t)(b * S + s0)) * H;
        const uint32_t sb0 = (uint32_t)__cvta_generic_to_shared(buf[0]);
        const uint32_t sb1 = (uint32_t)__cvta_generic_to_shared(buf[1]);

        // prime pipeline: 2 tiles deep
        issue_tile(rowbase, jbase, jend, sb0, tid); cp_commit();
        if (ntiles > 1) { issue_tile(rowbase, jbase + TILE, jend, sb1, tid); cp_commit(); }

        for (int i = tid; i < H; i += NTHREAD) swv[i] = w[i];
        if (tid == 0) sscal[1] = -INFINITY;

        float4 acc = make_float4(0.f, 0.f, 0.f, 0.f);   // my H-column (tid*4..tid*4+3)

        for (int t = 0; t < ntiles; t++) {
            if (t + 1 < ntiles) cp_wait1(); else cp_wait0();
            __syncthreads();                      // tile t visible (and w/sscal on t=0)

            const float* bt = buf[t & 1];
            // ---- scores: warp w -> row w of tile ----
            const int row = jbase + t * TILE + warp;
            float sc = -INFINITY;
            if (row < jend) {
                const float4* r4 = (const float4*)(bt + warp * H);
                const float4* w4 = (const float4*)swv;
                float d0 = 0.f, d1 = 0.f;
#pragma unroll
                for (int i = 0; i < 8; i += 2) {
                    float4 a = r4[lane + i * 32],     x = w4[lane + i * 32];
                    float4 c = r4[lane + (i+1) * 32], y = w4[lane + (i+1) * 32];
                    d0 += a.x * x.x + a.y * x.y + a.z * x.z + a.w * x.w;
                    d1 += c.x * y.x + c.y * y.y + c.z * y.z + c.w * y.w;
                }
                float dot = d0 + d1;
#pragma unroll
                for (int o = 16; o; o >>= 1) dot += __shfl_xor_sync(0xffffffffu, dot, o);
                sc = amb * dot;
            }
            if (lane == 0) sdot[warp] = sc;
            __syncthreads();

            // ---- warp 0: online-softmax scalars for this tile ----
            if (warp == 0) {
                const float m_old = sscal[1];
                float sj = (lane < TILE) ? sdot[lane] : -INFINITY;
                float mn = fmaxf(m_old, sj);
#pragma unroll
                for (int o = 16; o; o >>= 1) mn = fmaxf(mn, __shfl_xor_sync(0xffffffffu, mn, o));
                const float facv = __expf(m_old - mn);     // t=0: exp(-inf)=0
                const float pj = __expf(sj - mn);          // lanes>=8 -> 0
                if (lane < TILE) pbuf[lane] = pj;
                float psum = pj;
#pragma unroll
                for (int o = 16; o; o >>= 1) psum += __shfl_xor_sync(0xffffffffu, psum, o);
                if (lane == 0) {
                    sscal[0] = facv;
                    sscal[1] = mn;
                    l_acc = l_acc * facv + psum;
                    m_reg = mn;
                }
            }
            __syncthreads();

            // ---- accumulate: every thread updates its own float4 column ----
            const float facv = sscal[0];
            float p[TILE];
#pragma unroll
            for (int j = 0; j < TILE; j++) p[j] = pbuf[j];
            acc.x *= facv; acc.y *= facv; acc.z *= facv; acc.w *= facv;
#pragma unroll
            for (int j = 0; j < TILE; j++) {
                if (p[j] != 0.0f) {
                    float4 v = ((const float4*)(bt + j * H))[tid];
                    acc.x += p[j] * v.x; acc.y += p[j] * v.y;
                    acc.z += p[j] * v.z; acc.w += p[j] * v.w;
                }
            }
            __syncthreads();                       // buf[t&1] free for reuse

            if (t + 2 < ntiles) {
                issue_tile(rowbase, jbase + (t + 2) * TILE, jend, (t & 1) ? sb1 : sb0, tid);
                cp_commit();
            }
        }

        // ---- write block partial (no cross-warp merge needed) ----
        ((float4*)(g_pacc + (size_t)pidx * H))[tid] = acc;
        if (tid == 0) { g_pm[pidx] = m_reg; g_pl[pidx] = l_acc; }
    }

    // ---- arrival counting; last block of batch b combines ----
    __threadfence();
    __syncthreads();
    if (tid == 0)
        *s_last = ((atomicAdd(&g_cnt[b], 1u) & (NCHUNK - 1)) == (NCHUNK - 1)) ? 1u : 0u;
    __syncthreads();
    if (!*s_last) return;
    __threadfence();

    // ===== combine for batch b =====
    int maxlen = 0;
#pragma unroll
    for (int bb = 0; bb < B; bb++) {
        int ss, ee; qi_decode(qi, is64, bb, ss, ee);
        maxlen = max(maxlen, ee + 1 - ss);
    }
    const int   nact  = min(NCHUNK, (qlen + JC - 1) / JC);  // active chunks = prefix
    const float count = (float)(maxlen - qlen);             // zero-score tail rows

    // global max (seed 0: tail rows always exist, score 0)
    sred[tid] = (tid < nact) ? g_pm[b * NCHUNK + tid] : -INFINITY;
    __syncthreads();
#pragma unroll
    for (int o = NTHREAD / 2; o; o >>= 1) {
        if (tid < o) sred[tid] = fmaxf(sred[tid], sred[tid + o]);
        __syncthreads();
    }
    const float M = fmaxf(sred[0], 0.0f);
    __syncthreads();

    // per-chunk rescale factors + denominator
    float fv = 0.0f, flp = 0.0f;
    if (tid < nact) {
        fv  = __expf(g_pm[b * NCHUNK + tid] - M);
        flp = g_pl[b * NCHUNK + tid] * fv;
    }
    if (tid < NCHUNK) sfac[tid] = fv;
    sred[tid] = flp;
    __syncthreads();
#pragma unroll
    for (int o = NTHREAD / 2; o; o >>= 1) {
        if (tid < o) sred[tid] += sred[tid + o];
        __syncthreads();
    }
    const float L = count * __expf(-M) + sred[0];

    // numerator: thread owns float4 column tid (H/4 == NTHREAD)
    float4 a0 = make_float4(0.f, 0.f, 0.f, 0.f);
    for (int c = 0; c < nact; c++) {
        const float f = sfac[c];
        if (f != 0.0f) {
            float4 v = ((const float4*)(g_pacc + ((size_t)(b * NCHUNK + c)) * H))[tid];
            a0.x += f * v.x; a0.y += f * v.y; a0.z += f * v.z; a0.w += f * v.w;
        }
    }

    const float scale = am[b] / L;
    a0.x *= scale; a0.y *= scale; a0.z *= scale; a0.w *= scale;
    ((float4*)(out + (size_t)b * H))[tid] = a0;
}

extern "C" void kernel_launch(void* const* d_in, const int* in_sizes, int n_in,
                              void* d_out, int out_size) {
    // Identify inputs by element count (robust to metadata ordering).
    const float* hs = nullptr;
    const int*   qi = nullptr;
    const float* am = nullptr;
    const float* w  = nullptr;
    for (int i = 0; i < n_in; i++) {
        switch (in_sizes[i]) {
            case B * S * H: hs = (const float*)d_in[i]; break;
            case 2 * B:     qi = (const int*)d_in[i];   break;
            case B:         am = (const float*)d_in[i]; break;
            case H:         w  = (const float*)d_in[i]; break;
        }
    }
    float* out = (float*)d_out;

    const size_t smem = (2 * TILE * H + H + 8 + 8 + 2 + NTHREAD + NCHUNK) * sizeof(float) + 16;
    cudaFuncSetAttribute(k_main, cudaFuncAttributeMaxDynamicSharedMemorySize, (int)smem);

    dim3 grid(NCHUNK, B);
    k_main<<<grid, NTHREAD, smem>>>(hs, qi, am, w, out);
}